// round 15
// baseline (speedup 1.0000x reference)
#include <cuda_runtime.h>
#include <cstdint>

// Problem constants
#define B_ 32
#define T_ 1024
#define D_ 1024
#define S_ 128
#define H_ 4096
#define M_TOK (B_ * T_)   // 32768

// -------------------- scratch (device globals; no allocation) --------------------
__device__ float g_xln[(size_t)M_TOK * D_];   // 128 MB : LN1 output (fp32 residual)
__device__ float g_inj[(size_t)M_TOK * S_];   //  16 MB
__device__ float g_H  [(size_t)M_TOK * S_];   //  16 MB : scan states (tf32-rounded)
__device__ float g_x2 [(size_t)M_TOK * D_];   // 128 MB : x2 (tf32-rounded, MLP1 input)
__device__ float g_h1 [(size_t)M_TOK * H_];   // 512 MB : gelu(h1) (tf32-rounded, MLP2 input)
__device__ float g_x3 [(size_t)M_TOK * D_];   // 128 MB : MLP2 output (full fp32)
__device__ float g_w1r[(size_t)H_ * D_];      //  16 MB : tf32-rounded w1
__device__ float g_w2r[(size_t)D_ * H_];      //  16 MB : tf32-rounded w2
__device__ float g_ror[(size_t)D_ * S_];      // 0.5 MB : tf32-rounded readout

// -------------------- small PTX helpers --------------------
__device__ __forceinline__ void cp_async16(void* smem, const void* gmem) {
    unsigned sa = (unsigned)__cvta_generic_to_shared(smem);
    asm volatile("cp.async.cg.shared.global [%0], [%1], 16;\n" :: "r"(sa), "l"(gmem));
}
__device__ __forceinline__ void cp_commit() { asm volatile("cp.async.commit_group;\n" ::: "memory"); }
__device__ __forceinline__ void cp_wait0()  { asm volatile("cp.async.wait_group 0;\n" ::: "memory"); }

__device__ __forceinline__ uint32_t f2tf32(float x) {
    uint32_t r; asm("cvt.rna.tf32.f32 %0, %1;" : "=r"(r) : "f"(x)); return r;
}
__device__ __forceinline__ float rnd_tf32(float x) { return __uint_as_float(f2tf32(x)); }

__device__ __forceinline__ void mma_m16n8k8(float* c,
    uint32_t a0, uint32_t a1, uint32_t a2, uint32_t a3, uint32_t b0, uint32_t b1) {
    asm volatile(
        "mma.sync.aligned.m16n8k8.row.col.f32.tf32.tf32.f32 "
        "{%0,%1,%2,%3}, {%4,%5,%6,%7}, {%8,%9}, {%0,%1,%2,%3};\n"
        : "+f"(c[0]), "+f"(c[1]), "+f"(c[2]), "+f"(c[3])
        : "r"(a0), "r"(a1), "r"(a2), "r"(a3), "r"(b0), "r"(b1));
}
__device__ __forceinline__ unsigned long long fma_x2(
    unsigned long long a, unsigned long long b, unsigned long long c) {
    unsigned long long d;
    asm("fma.rn.f32x2 %0, %1, %2, %3;" : "=l"(d) : "l"(a), "l"(b), "l"(c));
    return d;
}
__device__ __forceinline__ unsigned long long add_x2(unsigned long long a, unsigned long long b) {
    unsigned long long d;
    asm("add.rn.f32x2 %0, %1, %2;" : "=l"(d) : "l"(a), "l"(b));
    return d;
}

// -------------------- LayerNorm (mode 0: LN, mode 1: x + LN(x)) --------------------
__global__ void ln_kernel(const float* __restrict__ x, const float* __restrict__ w,
                          const float* __restrict__ b, float* __restrict__ y, int addres) {
    __shared__ float red[16];
    const int row = blockIdx.x;
    const int tid = threadIdx.x;
    const float4* xr = (const float4*)(x + (size_t)row * D_);
    float4 v = xr[tid];
    float s = v.x + v.y + v.z + v.w;
    float q = v.x * v.x + v.y * v.y + v.z * v.z + v.w * v.w;
#pragma unroll
    for (int o = 16; o > 0; o >>= 1) {
        s += __shfl_xor_sync(0xffffffffu, s, o);
        q += __shfl_xor_sync(0xffffffffu, q, o);
    }
    if ((tid & 31) == 0) { red[tid >> 5] = s; red[8 + (tid >> 5)] = q; }
    __syncthreads();
    float S = 0.f, Q = 0.f;
#pragma unroll
    for (int i = 0; i < 8; i++) { S += red[i]; Q += red[8 + i]; }
    const float mu  = S * (1.0f / (float)D_);
    const float var = Q * (1.0f / (float)D_) - mu * mu;
    const float rs  = 1.0f / sqrtf(var + 1e-5f);
    float4 wv = ((const float4*)w)[tid];
    float4 bv = ((const float4*)b)[tid];
    float4 o;
    o.x = (v.x - mu) * rs * wv.x + bv.x;
    o.y = (v.y - mu) * rs * wv.y + bv.y;
    o.z = (v.z - mu) * rs * wv.z + bv.z;
    o.w = (v.w - mu) * rs * wv.w + bv.w;
    if (addres) { o.x += v.x; o.y += v.y; o.z += v.z; o.w += v.w; }
    ((float4*)(y + (size_t)row * D_))[tid] = o;
}

// -------------------- tf32 pre-round (weights) --------------------
__global__ void round_kernel(const float* __restrict__ w, float* __restrict__ o, int n) {
    int i = blockIdx.x * 256 + threadIdx.x;
    if (i < n) o[i] = rnd_tf32(w[i]);
}

// -------------------- 3xTF32 GEMM (inj only): C = A @ B^T --------------------
#define GBM 128
#define GBN 128
#define GBK 16
#define GLD 20

__device__ __forceinline__ void inj_load_tile(const float* Ag, const float* Bg,
                                              float* As, float* Bs, int K, int ko, int tid) {
    const int r0 = tid >> 2, c0 = tid & 3;
#pragma unroll
    for (int h = 0; h < 2; h++) {
        const int r = r0 + h * 64;
        cp_async16(As + r * GLD + c0 * 4, Ag + (size_t)r * K + ko + c0 * 4);
        cp_async16(Bs + r * GLD + c0 * 4, Bg + (size_t)r * K + ko + c0 * 4);
    }
}

__global__ __launch_bounds__(256, 1) void gemm_inj(
    const float* __restrict__ A, const float* __restrict__ Bw,
    float* __restrict__ C, int M, int N, int K) {
    __shared__ __align__(16) float As[2][GBM * GLD];
    __shared__ __align__(16) float Bs[2][GBN * GLD];

    const int tid  = threadIdx.x;
    const int lane = tid & 31, wid = tid >> 5;
    const int wm = wid & 1;
    const int wn = wid >> 1;
    const int lr = lane >> 2, lc = lane & 3;
    const int bm = blockIdx.y, bn = blockIdx.x;

    const float* Ag = A  + (size_t)bm * GBM * K;
    const float* Bg = Bw + (size_t)bn * GBN * K;

    float acc[4][4][4];
#pragma unroll
    for (int i = 0; i < 4; i++)
#pragma unroll
        for (int j = 0; j < 4; j++)
#pragma unroll
            for (int r = 0; r < 4; r++) acc[i][j][r] = 0.f;

    inj_load_tile(Ag, Bg, As[0], Bs[0], K, 0, tid);
    cp_commit(); cp_wait0(); __syncthreads();

    const int NT = K / GBK;
    int buf = 0;
    for (int kt = 0; kt < NT; kt++) {
        if (kt + 1 < NT) {
            inj_load_tile(Ag, Bg, As[buf ^ 1], Bs[buf ^ 1], K, (kt + 1) * GBK, tid);
            cp_commit();
        }
#pragma unroll
        for (int k8 = 0; k8 < 2; k8++) {
            const int kb = k8 * 8;
            uint32_t ah[4][4], al[4][4];
#pragma unroll
            for (int ma = 0; ma < 4; ma++) {
                const int rb = wm * 64 + ma * 16 + lr;
                float x0 = As[buf][(rb    ) * GLD + kb + lc    ];
                float x1 = As[buf][(rb + 8) * GLD + kb + lc    ];
                float x2 = As[buf][(rb    ) * GLD + kb + lc + 4];
                float x3 = As[buf][(rb + 8) * GLD + kb + lc + 4];
                ah[ma][0] = f2tf32(x0); al[ma][0] = f2tf32(x0 - __uint_as_float(ah[ma][0]));
                ah[ma][1] = f2tf32(x1); al[ma][1] = f2tf32(x1 - __uint_as_float(ah[ma][1]));
                ah[ma][2] = f2tf32(x2); al[ma][2] = f2tf32(x2 - __uint_as_float(ah[ma][2]));
                ah[ma][3] = f2tf32(x3); al[ma][3] = f2tf32(x3 - __uint_as_float(ah[ma][3]));
            }
            uint32_t bh[4][2], bl[4][2];
#pragma unroll
            for (int na = 0; na < 4; na++) {
                const int nb = wn * 32 + na * 8 + lr;
                float y0 = Bs[buf][nb * GLD + kb + lc    ];
                float y1 = Bs[buf][nb * GLD + kb + lc + 4];
                bh[na][0] = f2tf32(y0); bl[na][0] = f2tf32(y0 - __uint_as_float(bh[na][0]));
                bh[na][1] = f2tf32(y1); bl[na][1] = f2tf32(y1 - __uint_as_float(bh[na][1]));
            }
#pragma unroll
            for (int ma = 0; ma < 4; ma++)
#pragma unroll
                for (int na = 0; na < 4; na++) {
                    float* c = acc[ma][na];
                    mma_m16n8k8(c, al[ma][0], al[ma][1], al[ma][2], al[ma][3], bh[na][0], bh[na][1]);
                    mma_m16n8k8(c, ah[ma][0], ah[ma][1], ah[ma][2], ah[ma][3], bl[na][0], bl[na][1]);
                    mma_m16n8k8(c, ah[ma][0], ah[ma][1], ah[ma][2], ah[ma][3], bh[na][0], bh[na][1]);
                }
        }
        if (kt + 1 < NT) cp_wait0();
        __syncthreads();
        buf ^= 1;
    }

#pragma unroll
    for (int ma = 0; ma < 4; ma++) {
        const int row = bm * GBM + wm * 64 + ma * 16 + lr;
#pragma unroll
        for (int na = 0; na < 4; na++) {
            const int col = bn * GBN + wn * 32 + na * 8 + lc * 2;
#pragma unroll
            for (int h = 0; h < 2; h++) {
                const int rr = row + h * 8;
                const size_t idx = (size_t)rr * N + col;
                *(float2*)(C + idx) = make_float2(acc[ma][na][2 * h], acc[ma][na][2 * h + 1]);
            }
        }
    }
}

// -------------------- fast single-pass TF32 GEMM: C = A @ B^T --------------------
// Inputs A, B are PRE-ROUNDED to tf32 (raw fp32 bits fed to MMA, no inner cvt).
// k-permutation: logical k=tg <-> phys col 2tg; k=tg+4 <-> phys 2tg+1 (applied to
// both A and B -> result unchanged) so each fragment is one 64-bit LDS.
// MODE 1: v = c + X[m*N+n]        ; store rnd_tf32(v)   (readout + residual)
// MODE 2: v = gelu(c + bias[n])   ; store rnd_tf32(v)   (MLP1)
// MODE 3: v = c + bias[n]         ; store v (fp32)      (MLP2)
#define FBM 128
#define FBN 128
#define FBK 32
#define FLD 40                               // floats per smem row (32 + 8 pad): bases 8g mod 32
#define FTILE (FBM * FLD)                    // floats per operand tile
#define FSMEM (2 * 2 * FTILE * 4)            // bytes: 2 stages x (A,B) = 81920

__device__ __forceinline__ void fast_load(const float* Ag, const float* Bg,
                                          float* As, float* Bs, int K, int ko, int tid) {
    const int r  = tid >> 1;
    const int c0 = (tid & 1) * 16;           // float offset within row
    const float* sa = Ag + (size_t)r * K + ko + c0;
    const float* sb = Bg + (size_t)r * K + ko + c0;
    float* da = As + r * FLD + c0;
    float* db = Bs + r * FLD + c0;
#pragma unroll
    for (int j = 0; j < 4; j++) {
        cp_async16(da + j * 4, sa + j * 4);
        cp_async16(db + j * 4, sb + j * 4);
    }
}

template <int MODE>
__global__ __launch_bounds__(256, 2) void gemm_fast(
    const float* __restrict__ A, const float* __restrict__ Bw,
    float* __restrict__ C, const float* __restrict__ X,
    int M, int N, int K) {
    extern __shared__ __align__(16) float fsm[];
    // layout: stage s: A at s*2*FTILE, B at s*2*FTILE + FTILE

    const int tid  = threadIdx.x;
    const int lane = tid & 31, wid = tid >> 5;
    const int wm = wid & 1;          // 2 warp rows (64 rows)
    const int wn = wid >> 1;         // 4 warp cols (32 cols)
    const int lr = lane >> 2, lc = lane & 3;
    const int bm = blockIdx.y, bn = blockIdx.x;

    const float* Ag = A  + (size_t)bm * FBM * K;
    const float* Bg = Bw + (size_t)bn * FBN * K;

    float acc[4][4][4];
#pragma unroll
    for (int i = 0; i < 4; i++)
#pragma unroll
        for (int j = 0; j < 4; j++)
#pragma unroll
            for (int r = 0; r < 4; r++) acc[i][j][r] = 0.f;

    fast_load(Ag, Bg, fsm, fsm + FTILE, K, 0, tid);
    cp_commit(); cp_wait0(); __syncthreads();

    const int NT = K / FBK;
    int buf = 0;
    for (int kt = 0; kt < NT; kt++) {
        float* Asb = fsm + (buf ^ 1) * 2 * FTILE;
        if (kt + 1 < NT) {
            fast_load(Ag, Bg, Asb, Asb + FTILE, K, (kt + 1) * FBK, tid);
            cp_commit();
        }
        const float* As = fsm + buf * 2 * FTILE;
        const float* Bs = As + FTILE;
#pragma unroll
        for (int k8 = 0; k8 < 4; k8++) {
            const int kb = k8 * 8 + 2 * lc;   // phys col pair (2lc, 2lc+1)
            uint32_t a[4][4];
#pragma unroll
            for (int ma = 0; ma < 4; ma++) {
                const int rb = wm * 64 + ma * 16 + lr;
                float2 p = *(const float2*)(As + (size_t)rb * FLD + kb);        // a0, a2
                float2 q = *(const float2*)(As + (size_t)(rb + 8) * FLD + kb);  // a1, a3
                a[ma][0] = __float_as_uint(p.x);
                a[ma][1] = __float_as_uint(q.x);
                a[ma][2] = __float_as_uint(p.y);
                a[ma][3] = __float_as_uint(q.y);
            }
            uint32_t bfr[4][2];
#pragma unroll
            for (int na = 0; na < 4; na++) {
                const int nb = wn * 32 + na * 8 + lr;
                float2 y = *(const float2*)(Bs + (size_t)nb * FLD + kb);        // b0, b1
                bfr[na][0] = __float_as_uint(y.x);
                bfr[na][1] = __float_as_uint(y.y);
            }
#pragma unroll
            for (int ma = 0; ma < 4; ma++)
#pragma unroll
                for (int na = 0; na < 4; na++)
                    mma_m16n8k8(acc[ma][na], a[ma][0], a[ma][1], a[ma][2], a[ma][3],
                                bfr[na][0], bfr[na][1]);
        }
        if (kt + 1 < NT) cp_wait0();
        __syncthreads();
        buf ^= 1;
    }

    // epilogue
#pragma unroll
    for (int ma = 0; ma < 4; ma++) {
        const int row = bm * FBM + wm * 64 + ma * 16 + lr;
#pragma unroll
        for (int na = 0; na < 4; na++) {
            const int col = bn * FBN + wn * 32 + na * 8 + lc * 2;
#pragma unroll
            for (int h = 0; h < 2; h++) {
                const int rr = row + h * 8;
                const size_t idx = (size_t)rr * N + col;
                float2 v = make_float2(acc[ma][na][2 * h], acc[ma][na][2 * h + 1]);
                if (MODE == 1) {
                    float2 xv = *(const float2*)(X + idx);
                    v.x = rnd_tf32(v.x + xv.x);
                    v.y = rnd_tf32(v.y + xv.y);
                } else if (MODE == 2) {
                    v.x += X[col];
                    v.y += X[col + 1];
                    v.x = rnd_tf32(0.5f * v.x * (1.0f + erff(v.x * 0.70710678118654752f)));
                    v.y = rnd_tf32(0.5f * v.y * (1.0f + erff(v.y * 0.70710678118654752f)));
                } else {               // MODE 3
                    v.x += X[col];
                    v.y += X[col + 1];
                }
                *(float2*)(C + idx) = v;
            }
        }
    }
}

// -------------------- sequential state scan --------------------
__global__ __launch_bounds__(256, 1) void scan_kernel(
    const float* __restrict__ inj, const float* __restrict__ gate_w,
    const float* __restrict__ gate_b, const float* __restrict__ flow,
    float* __restrict__ Hst) {
    const int b   = blockIdx.x;
    const int tid = threadIdx.x;
    const int s   = tid & 127;
    const int grp = tid >> 7;

    __shared__ __align__(16) float hbuf[2][S_];
    __shared__ float fbuf[S_];

    const float* W = (grp == 0) ? gate_w : flow;
    unsigned long long wr[64];
    const ulonglong2* wrow = (const ulonglong2*)(W + (size_t)s * S_);
#pragma unroll
    for (int i = 0; i < 32; i++) { ulonglong2 t2 = wrow[i]; wr[2 * i] = t2.x; wr[2 * i + 1] = t2.y; }

    if (tid < S_) hbuf[0][tid] = 0.0f;
    __syncthreads();

    const float bias = (grp == 0) ? gate_b[s] : 0.0f;
    const float* injp = inj + ((size_t)b * T_) * S_ + s;
    float* Hp = Hst + ((size_t)b * T_) * S_ + s;
    float inj_next = (grp == 0) ? injp[0] : 0.0f;

    int cur = 0;
    for (int t = 0; t < T_; t++) {
        const float inj_cur = inj_next;
        if (grp == 0 && t < T_ - 1) inj_next = injp[(size_t)(t + 1) * S_];

        unsigned long long a0 = 0ull, a1 = 0ull, a2 = 0ull, a3 = 0ull;
        const ulonglong2* h2 = (const ulonglong2*)hbuf[cur];
#pragma unroll
        for (int i = 0; i < 16; i++) {
            ulonglong2 hv = h2[2 * i];
            ulonglong2 hw = h2[2 * i + 1];
            a0 = fma_x2(hv.x, wr[4 * i + 0], a0);
            a1 = fma_x2(hv.y, wr[4 * i + 1], a1);
            a2 = fma_x2(hw.x, wr[4 * i + 2], a2);
            a3 = fma_x2(hw.y, wr[4 * i + 3], a3);
        }
        a0 = add_x2(a0, a1); a2 = add_x2(a2, a3); a0 = add_x2(a0, a2);
        float lo, hi;
        asm("mov.b64 {%0,%1}, %2;" : "=f"(lo), "=f"(hi) : "l"(a0));
        const float dot = lo + hi;

        if (grp == 1) fbuf[s] = dot;
        __syncthreads();
        if (grp == 0) {
            const float pre = dot + bias + inj_cur;
            const float g   = 1.0f / (1.0f + expf(-pre));
            const float hp  = hbuf[cur][s];
            const float hn  = hp + g * (fbuf[s] - hp);
            hbuf[cur ^ 1][s] = hn;
            Hp[(size_t)t * S_] = rnd_tf32(hn);   // readout GEMM consumes pre-rounded h
        }
        __syncthreads();
        cur ^= 1;
    }
}

// -------------------- launch --------------------
extern "C" void kernel_launch(void* const* d_in, const int* in_sizes, int n_in,
                              void* d_out, int out_size) {
    const float* x       = (const float*)d_in[0];
    const float* ln1w    = (const float*)d_in[1];
    const float* ln1b    = (const float*)d_in[2];
    const float* flow    = (const float*)d_in[3];
    const float* injw    = (const float*)d_in[4];
    const float* readout = (const float*)d_in[5];
    const float* gatew   = (const float*)d_in[6];
    const float* gateb   = (const float*)d_in[7];
    const float* w1      = (const float*)d_in[8];
    const float* b1      = (const float*)d_in[9];
    const float* w2      = (const float*)d_in[10];
    const float* b2      = (const float*)d_in[11];
    const float* ln2w    = (const float*)d_in[12];
    const float* ln2b    = (const float*)d_in[13];
    float* out = (float*)d_out;

    float *xln, *inj, *Hst, *x2, *h1, *x3, *w1r, *w2r, *ror;
    cudaGetSymbolAddress((void**)&xln, g_xln);
    cudaGetSymbolAddress((void**)&inj, g_inj);
    cudaGetSymbolAddress((void**)&Hst, g_H);
    cudaGetSymbolAddress((void**)&x2,  g_x2);
    cudaGetSymbolAddress((void**)&h1,  g_h1);
    cudaGetSymbolAddress((void**)&x3,  g_x3);
    cudaGetSymbolAddress((void**)&w1r, g_w1r);
    cudaGetSymbolAddress((void**)&w2r, g_w2r);
    cudaGetSymbolAddress((void**)&ror, g_ror);

    cudaFuncSetAttribute(gemm_fast<1>, cudaFuncAttributeMaxDynamicSharedMemorySize, FSMEM);
    cudaFuncSetAttribute(gemm_fast<2>, cudaFuncAttributeMaxDynamicSharedMemorySize, FSMEM);
    cudaFuncSetAttribute(gemm_fast<3>, cudaFuncAttributeMaxDynamicSharedMemorySize, FSMEM);

    const int M = M_TOK;

    // 1) xln = LN1(x)
    ln_kernel<<<M, 256>>>(x, ln1w, ln1b, xln, 0);
    // 1b) pre-round weights to tf32 (zero low mantissa bits)
    round_kernel<<<(H_ * D_) / 256, 256>>>(w1, w1r, H_ * D_);
    round_kernel<<<(D_ * H_) / 256, 256>>>(w2, w2r, D_ * H_);
    round_kernel<<<(D_ * S_) / 256, 256>>>(readout, ror, D_ * S_);
    // 2) inj = xln @ injection^T   (feeds recurrent scan -> 3xTF32 accuracy)
    gemm_inj<<<dim3(S_ / GBN, M / GBM), 256>>>(xln, injw, inj, M, S_, D_);
    // 3) sequential scan -> Hst (tf32-rounded at store)
    scan_kernel<<<B_, 256>>>(inj, gatew, gateb, flow, Hst);
    // 4) x2 = rnd(xln + Hst @ readout^T)
    gemm_fast<1><<<dim3(D_ / FBN, M / FBM), 256, FSMEM>>>(Hst, ror, x2, xln, M, D_, S_);
    // 5) h1 = rnd(gelu(x2 @ w1^T + b1))
    gemm_fast<2><<<dim3(H_ / FBN, M / FBM), 256, FSMEM>>>(x2, w1r, h1, b1, M, H_, D_);
    // 6) x3 = h1 @ w2^T + b2  (full fp32)
    gemm_fast<3><<<dim3(D_ / FBN, M / FBM), 256, FSMEM>>>(h1, w2r, x3, b2, M, D_, H_);
    // 7) out = x3 + LN2(x3)
    ln_kernel<<<M, 256>>>(x3, ln2w, ln2b, out, 1);
}

// round 16
// speedup vs baseline: 1.1741x; 1.1741x over previous
#include <cuda_runtime.h>
#include <cstdint>

// Problem constants
#define B_ 32
#define T_ 1024
#define D_ 1024
#define S_ 128
#define H_ 4096
#define M_TOK (B_ * T_)   // 32768

// -------------------- scratch (device globals; no allocation) --------------------
__device__ float g_xln[(size_t)M_TOK * D_];   // 128 MB : LN1 output (fp32 residual)
__device__ float g_inj[(size_t)M_TOK * S_];   //  16 MB
__device__ float g_H  [(size_t)M_TOK * S_];   //  16 MB : scan states (tf32-rounded)
__device__ float g_x2 [(size_t)M_TOK * D_];   // 128 MB : x2 (tf32-rounded, MLP1 input)
__device__ float g_h1 [(size_t)M_TOK * H_];   // 512 MB : gelu(h1) (tf32-rounded, MLP2 input)
__device__ float g_x3 [(size_t)M_TOK * D_];   // 128 MB : MLP2 output (full fp32)
__device__ float g_w1r[(size_t)H_ * D_];      //  16 MB : tf32-rounded w1
__device__ float g_w2r[(size_t)D_ * H_];      //  16 MB : tf32-rounded w2
__device__ float g_ror[(size_t)D_ * S_];      // 0.5 MB : tf32-rounded readout

// -------------------- small PTX helpers --------------------
__device__ __forceinline__ void cp_async16(void* smem, const void* gmem) {
    unsigned sa = (unsigned)__cvta_generic_to_shared(smem);
    asm volatile("cp.async.cg.shared.global [%0], [%1], 16;\n" :: "r"(sa), "l"(gmem));
}
__device__ __forceinline__ void cp_commit() { asm volatile("cp.async.commit_group;\n" ::: "memory"); }
__device__ __forceinline__ void cp_wait0()  { asm volatile("cp.async.wait_group 0;\n" ::: "memory"); }

__device__ __forceinline__ uint32_t f2tf32(float x) {
    uint32_t r; asm("cvt.rna.tf32.f32 %0, %1;" : "=r"(r) : "f"(x)); return r;
}
__device__ __forceinline__ float rnd_tf32(float x) { return __uint_as_float(f2tf32(x)); }

__device__ __forceinline__ void mma_m16n8k8(float* c,
    uint32_t a0, uint32_t a1, uint32_t a2, uint32_t a3, uint32_t b0, uint32_t b1) {
    asm volatile(
        "mma.sync.aligned.m16n8k8.row.col.f32.tf32.tf32.f32 "
        "{%0,%1,%2,%3}, {%4,%5,%6,%7}, {%8,%9}, {%0,%1,%2,%3};\n"
        : "+f"(c[0]), "+f"(c[1]), "+f"(c[2]), "+f"(c[3])
        : "r"(a0), "r"(a1), "r"(a2), "r"(a3), "r"(b0), "r"(b1));
}
__device__ __forceinline__ unsigned long long fma_x2(
    unsigned long long a, unsigned long long b, unsigned long long c) {
    unsigned long long d;
    asm("fma.rn.f32x2 %0, %1, %2, %3;" : "=l"(d) : "l"(a), "l"(b), "l"(c));
    return d;
}
__device__ __forceinline__ unsigned long long add_x2(unsigned long long a, unsigned long long b) {
    unsigned long long d;
    asm("add.rn.f32x2 %0, %1, %2;" : "=l"(d) : "l"(a), "l"(b));
    return d;
}

// -------------------- LayerNorm (mode 0: LN, mode 1: x + LN(x)) --------------------
__global__ void ln_kernel(const float* __restrict__ x, const float* __restrict__ w,
                          const float* __restrict__ b, float* __restrict__ y, int addres) {
    __shared__ float red[16];
    const int row = blockIdx.x;
    const int tid = threadIdx.x;
    const float4* xr = (const float4*)(x + (size_t)row * D_);
    float4 v = xr[tid];
    float s = v.x + v.y + v.z + v.w;
    float q = v.x * v.x + v.y * v.y + v.z * v.z + v.w * v.w;
#pragma unroll
    for (int o = 16; o > 0; o >>= 1) {
        s += __shfl_xor_sync(0xffffffffu, s, o);
        q += __shfl_xor_sync(0xffffffffu, q, o);
    }
    if ((tid & 31) == 0) { red[tid >> 5] = s; red[8 + (tid >> 5)] = q; }
    __syncthreads();
    float S = 0.f, Q = 0.f;
#pragma unroll
    for (int i = 0; i < 8; i++) { S += red[i]; Q += red[8 + i]; }
    const float mu  = S * (1.0f / (float)D_);
    const float var = Q * (1.0f / (float)D_) - mu * mu;
    const float rs  = 1.0f / sqrtf(var + 1e-5f);
    float4 wv = ((const float4*)w)[tid];
    float4 bv = ((const float4*)b)[tid];
    float4 o;
    o.x = (v.x - mu) * rs * wv.x + bv.x;
    o.y = (v.y - mu) * rs * wv.y + bv.y;
    o.z = (v.z - mu) * rs * wv.z + bv.z;
    o.w = (v.w - mu) * rs * wv.w + bv.w;
    if (addres) { o.x += v.x; o.y += v.y; o.z += v.z; o.w += v.w; }
    ((float4*)(y + (size_t)row * D_))[tid] = o;
}

// -------------------- tf32 pre-round (weights) --------------------
__global__ void round_kernel(const float* __restrict__ w, float* __restrict__ o, int n) {
    int i = blockIdx.x * 256 + threadIdx.x;
    if (i < n) o[i] = rnd_tf32(w[i]);
}

// -------------------- TF32 GEMM: C[M,N] = A[M,K] @ Bw[N,K]^T (+ epilogue) --------------------
// PASSES 3: hi/lo 3xTF32 from raw fp32 inputs (inj GEMM; near-fp32 accuracy)
// PASSES 1: single-pass; inputs MUST be pre-rounded to tf32 (raw bits fed to MMA, no cvt)
// MODE 0: store C (fp32)
// MODE 1: v = C + X[m*N+n]      ; store rnd_tf32(v)  (readout + residual -> x2)
// MODE 2: v = gelu(C + X[n])    ; store rnd_tf32(v)  (MLP1 -> h1)
// MODE 3: v = C + X[n]          ; store v fp32       (MLP2 -> x3)
#define GBM 128
#define GBN 128
#define GBK 16
#define GLD 20   // smem row stride (floats): BK + 4 pad

__device__ __forceinline__ void gemm_load_tile(const float* Ag, const float* Bg,
                                               float* As, float* Bs, int K, int ko, int tid) {
    const int r0 = tid >> 2, c0 = tid & 3;
#pragma unroll
    for (int h = 0; h < 2; h++) {
        const int r = r0 + h * 64;
        cp_async16(As + r * GLD + c0 * 4, Ag + (size_t)r * K + ko + c0 * 4);
        cp_async16(Bs + r * GLD + c0 * 4, Bg + (size_t)r * K + ko + c0 * 4);
    }
}

template <int MODE, int PASSES>
__global__ __launch_bounds__(256, (PASSES == 1) ? 2 : 1) void gemm_tf32(
    const float* __restrict__ A, const float* __restrict__ Bw,
    float* __restrict__ C, const float* __restrict__ X,
    int M, int N, int K) {
    __shared__ __align__(16) float As[2][GBM * GLD];
    __shared__ __align__(16) float Bs[2][GBN * GLD];

    const int tid  = threadIdx.x;
    const int lane = tid & 31, wid = tid >> 5;
    const int wm = wid & 1;        // 2 warp rows (64 rows each)
    const int wn = wid >> 1;       // 4 warp cols (32 cols each)
    const int lr = lane >> 2, lc = lane & 3;
    const int bm = blockIdx.y, bn = blockIdx.x;

    const float* Ag = A  + (size_t)bm * GBM * K;
    const float* Bg = Bw + (size_t)bn * GBN * K;

    float acc[4][4][4];
#pragma unroll
    for (int i = 0; i < 4; i++)
#pragma unroll
        for (int j = 0; j < 4; j++)
#pragma unroll
            for (int r = 0; r < 4; r++) acc[i][j][r] = 0.f;

    gemm_load_tile(Ag, Bg, As[0], Bs[0], K, 0, tid);
    cp_commit(); cp_wait0(); __syncthreads();

    const int NT = K / GBK;
    int buf = 0;
    for (int kt = 0; kt < NT; kt++) {
        if (kt + 1 < NT) {
            gemm_load_tile(Ag, Bg, As[buf ^ 1], Bs[buf ^ 1], K, (kt + 1) * GBK, tid);
            cp_commit();
        }
#pragma unroll
        for (int k8 = 0; k8 < 2; k8++) {
            const int kb = k8 * 8;
            uint32_t ah[4][4], al[4][4];
#pragma unroll
            for (int ma = 0; ma < 4; ma++) {
                const int rb = wm * 64 + ma * 16 + lr;
                float x0 = As[buf][(rb    ) * GLD + kb + lc    ];
                float x1 = As[buf][(rb + 8) * GLD + kb + lc    ];
                float x2 = As[buf][(rb    ) * GLD + kb + lc + 4];
                float x3 = As[buf][(rb + 8) * GLD + kb + lc + 4];
                if (PASSES == 3) {
                    ah[ma][0] = f2tf32(x0); al[ma][0] = f2tf32(x0 - __uint_as_float(ah[ma][0]));
                    ah[ma][1] = f2tf32(x1); al[ma][1] = f2tf32(x1 - __uint_as_float(ah[ma][1]));
                    ah[ma][2] = f2tf32(x2); al[ma][2] = f2tf32(x2 - __uint_as_float(ah[ma][2]));
                    ah[ma][3] = f2tf32(x3); al[ma][3] = f2tf32(x3 - __uint_as_float(ah[ma][3]));
                } else {
                    // inputs pre-rounded to tf32: feed raw bits, no cvt
                    ah[ma][0] = __float_as_uint(x0);
                    ah[ma][1] = __float_as_uint(x1);
                    ah[ma][2] = __float_as_uint(x2);
                    ah[ma][3] = __float_as_uint(x3);
                }
            }
            uint32_t bh[4][2], bl[4][2];
#pragma unroll
            for (int na = 0; na < 4; na++) {
                const int nb = wn * 32 + na * 8 + lr;
                float y0 = Bs[buf][nb * GLD + kb + lc    ];
                float y1 = Bs[buf][nb * GLD + kb + lc + 4];
                if (PASSES == 3) {
                    bh[na][0] = f2tf32(y0); bl[na][0] = f2tf32(y0 - __uint_as_float(bh[na][0]));
                    bh[na][1] = f2tf32(y1); bl[na][1] = f2tf32(y1 - __uint_as_float(bh[na][1]));
                } else {
                    bh[na][0] = __float_as_uint(y0);
                    bh[na][1] = __float_as_uint(y1);
                }
            }
#pragma unroll
            for (int ma = 0; ma < 4; ma++)
#pragma unroll
                for (int na = 0; na < 4; na++) {
                    float* c = acc[ma][na];
                    if (PASSES == 3) {
                        mma_m16n8k8(c, al[ma][0], al[ma][1], al[ma][2], al[ma][3], bh[na][0], bh[na][1]);
                        mma_m16n8k8(c, ah[ma][0], ah[ma][1], ah[ma][2], ah[ma][3], bl[na][0], bl[na][1]);
                    }
                    mma_m16n8k8(c, ah[ma][0], ah[ma][1], ah[ma][2], ah[ma][3], bh[na][0], bh[na][1]);
                }
        }
        if (kt + 1 < NT) cp_wait0();
        __syncthreads();
        buf ^= 1;
    }

    // epilogue (float2-vectorized)
#pragma unroll
    for (int ma = 0; ma < 4; ma++) {
        const int row = bm * GBM + wm * 64 + ma * 16 + lr;
#pragma unroll
        for (int na = 0; na < 4; na++) {
            const int col = bn * GBN + wn * 32 + na * 8 + lc * 2;
#pragma unroll
            for (int h = 0; h < 2; h++) {
                const int rr = row + h * 8;
                const size_t idx = (size_t)rr * N + col;
                float2 v = make_float2(acc[ma][na][2 * h], acc[ma][na][2 * h + 1]);
                if (MODE == 1) {
                    float2 xv = *(const float2*)(X + idx);
                    v.x = rnd_tf32(v.x + xv.x);
                    v.y = rnd_tf32(v.y + xv.y);
                } else if (MODE == 2) {
                    v.x += X[col];
                    v.y += X[col + 1];
                    v.x = rnd_tf32(0.5f * v.x * (1.0f + erff(v.x * 0.70710678118654752f)));
                    v.y = rnd_tf32(0.5f * v.y * (1.0f + erff(v.y * 0.70710678118654752f)));
                } else if (MODE == 3) {
                    v.x += X[col];
                    v.y += X[col + 1];
                }
                *(float2*)(C + idx) = v;
            }
        }
    }
}

// -------------------- sequential state scan --------------------
__global__ __launch_bounds__(256, 1) void scan_kernel(
    const float* __restrict__ inj, const float* __restrict__ gate_w,
    const float* __restrict__ gate_b, const float* __restrict__ flow,
    float* __restrict__ Hst) {
    const int b   = blockIdx.x;
    const int tid = threadIdx.x;
    const int s   = tid & 127;
    const int grp = tid >> 7;

    __shared__ __align__(16) float hbuf[2][S_];
    __shared__ float fbuf[S_];

    const float* W = (grp == 0) ? gate_w : flow;
    unsigned long long wr[64];
    const ulonglong2* wrow = (const ulonglong2*)(W + (size_t)s * S_);
#pragma unroll
    for (int i = 0; i < 32; i++) { ulonglong2 t2 = wrow[i]; wr[2 * i] = t2.x; wr[2 * i + 1] = t2.y; }

    if (tid < S_) hbuf[0][tid] = 0.0f;
    __syncthreads();

    const float bias = (grp == 0) ? gate_b[s] : 0.0f;
    const float* injp = inj + ((size_t)b * T_) * S_ + s;
    float* Hp = Hst + ((size_t)b * T_) * S_ + s;
    float inj_next = (grp == 0) ? injp[0] : 0.0f;

    int cur = 0;
    for (int t = 0; t < T_; t++) {
        const float inj_cur = inj_next;
        if (grp == 0 && t < T_ - 1) inj_next = injp[(size_t)(t + 1) * S_];

        unsigned long long a0 = 0ull, a1 = 0ull, a2 = 0ull, a3 = 0ull;
        const ulonglong2* h2 = (const ulonglong2*)hbuf[cur];
#pragma unroll
        for (int i = 0; i < 16; i++) {
            ulonglong2 hv = h2[2 * i];
            ulonglong2 hw = h2[2 * i + 1];
            a0 = fma_x2(hv.x, wr[4 * i + 0], a0);
            a1 = fma_x2(hv.y, wr[4 * i + 1], a1);
            a2 = fma_x2(hw.x, wr[4 * i + 2], a2);
            a3 = fma_x2(hw.y, wr[4 * i + 3], a3);
        }
        a0 = add_x2(a0, a1); a2 = add_x2(a2, a3); a0 = add_x2(a0, a2);
        float lo, hi;
        asm("mov.b64 {%0,%1}, %2;" : "=f"(lo), "=f"(hi) : "l"(a0));
        const float dot = lo + hi;

        if (grp == 1) fbuf[s] = dot;
        __syncthreads();
        if (grp == 0) {
            const float pre = dot + bias + inj_cur;
            const float g   = 1.0f / (1.0f + expf(-pre));
            const float hp  = hbuf[cur][s];
            const float hn  = hp + g * (fbuf[s] - hp);
            hbuf[cur ^ 1][s] = hn;
            Hp[(size_t)t * S_] = rnd_tf32(hn);   // readout GEMM consumes pre-rounded h
        }
        __syncthreads();
        cur ^= 1;
    }
}

// -------------------- launch --------------------
extern "C" void kernel_launch(void* const* d_in, const int* in_sizes, int n_in,
                              void* d_out, int out_size) {
    const float* x       = (const float*)d_in[0];
    const float* ln1w    = (const float*)d_in[1];
    const float* ln1b    = (const float*)d_in[2];
    const float* flow    = (const float*)d_in[3];
    const float* injw    = (const float*)d_in[4];
    const float* readout = (const float*)d_in[5];
    const float* gatew   = (const float*)d_in[6];
    const float* gateb   = (const float*)d_in[7];
    const float* w1      = (const float*)d_in[8];
    const float* b1      = (const float*)d_in[9];
    const float* w2      = (const float*)d_in[10];
    const float* b2      = (const float*)d_in[11];
    const float* ln2w    = (const float*)d_in[12];
    const float* ln2b    = (const float*)d_in[13];
    float* out = (float*)d_out;

    float *xln, *inj, *Hst, *x2, *h1, *x3, *w1r, *w2r, *ror;
    cudaGetSymbolAddress((void**)&xln, g_xln);
    cudaGetSymbolAddress((void**)&inj, g_inj);
    cudaGetSymbolAddress((void**)&Hst, g_H);
    cudaGetSymbolAddress((void**)&x2,  g_x2);
    cudaGetSymbolAddress((void**)&h1,  g_h1);
    cudaGetSymbolAddress((void**)&x3,  g_x3);
    cudaGetSymbolAddress((void**)&w1r, g_w1r);
    cudaGetSymbolAddress((void**)&w2r, g_w2r);
    cudaGetSymbolAddress((void**)&ror, g_ror);

    const int M = M_TOK;

    // 1) xln = LN1(x)
    ln_kernel<<<M, 256>>>(x, ln1w, ln1b, xln, 0);
    // 1b) pre-round weights to tf32 (zero low mantissa bits; cvt leaves the GEMM hot loop)
    round_kernel<<<(H_ * D_) / 256, 256>>>(w1, w1r, H_ * D_);
    round_kernel<<<(D_ * H_) / 256, 256>>>(w2, w2r, D_ * H_);
    round_kernel<<<(D_ * S_) / 256, 256>>>(readout, ror, D_ * S_);
    // 2) inj = xln @ injection^T   (feeds recurrent scan -> 3xTF32 accuracy)
    gemm_tf32<0, 3><<<dim3(S_ / GBN, M / GBM), 256>>>(xln, injw, inj, nullptr, M, S_, D_);
    // 3) sequential scan -> Hst (tf32-rounded at store)
    scan_kernel<<<B_, 256>>>(inj, gatew, gateb, flow, Hst);
    // 4) x2 = rnd(xln + Hst @ readout^T)
    gemm_tf32<1, 1><<<dim3(D_ / GBN, M / GBM), 256>>>(Hst, ror, x2, xln, M, D_, S_);
    // 5) h1 = rnd(gelu(x2 @ w1^T + b1))
    gemm_tf32<2, 1><<<dim3(H_ / GBN, M / GBM), 256>>>(x2, w1r, h1, b1, M, H_, D_);
    // 6) x3 = h1 @ w2^T + b2  (full fp32)
    gemm_tf32<3, 1><<<dim3(D_ / GBN, M / GBM), 256>>>(h1, w2r, x3, b2, M, D_, H_);
    // 7) out = x3 + LN2(x3)
    ln_kernel<<<M, 256>>>(x3, ln2w, ln2b, out, 1);
}